// round 13
// baseline (speedup 1.0000x reference)
#include <cuda_runtime.h>
#include <cstdint>
#include <cstring>

// Problem constants
#define BB     4096
#define D_IN   128
#define HID    200
#define DIMV   256
#define MM     32

#define B1_STRIDE 40    // pad: bank = 8t+g (+8mt) -> conflict-free
#define Q2_STRIDE 264   // pad: bank = 8t+g+8nt   -> conflict-free
#define B1_WORDS (128 * B1_STRIDE)   // 5120
#define Q2_WORDS (16 * Q2_STRIDE)    // 4224

// Scratch (device globals — no allocation allowed)
__device__ float g_H1[BB * HID];
__device__ float g_H2[BB * HID];
__device__ float g_Y [BB * DIMV];
__device__ float g_Q [MM * DIMV];
__device__ uint32_t g_B1hi[B1_WORDS];   // A^T packed bf16x2 (hi), fragment order
__device__ uint32_t g_B1lo[B1_WORDS];
__device__ uint32_t g_Q2hi[Q2_WORDS];   // Q packed bf16x2 (hi)
__device__ uint32_t g_Q2lo[Q2_WORDS];

// ---------------------------------------------------------------------------
// bf16 split-pack: x = hi + lo, packed as bf16x2 {x0 in low half, x1 in high}.
// ---------------------------------------------------------------------------
static __device__ __forceinline__ void bf16_split_pack(float x0, float x1,
                                                       uint32_t& hi, uint32_t& lo) {
    uint32_t h;
    asm("cvt.rn.bf16x2.f32 %0, %1, %2;" : "=r"(h) : "f"(x1), "f"(x0));
    float h0 = __uint_as_float(h << 16);
    float h1 = __uint_as_float(h & 0xFFFF0000u);
    float r0 = x0 - h0;
    float r1 = x1 - h1;
    uint32_t l;
    asm("cvt.rn.bf16x2.f32 %0, %1, %2;" : "=r"(l) : "f"(r1), "f"(r0));
    hi = h; lo = l;
}

static __device__ __forceinline__ void mma_bf16(float c[4], const uint32_t a[4],
                                                const uint32_t b[2]) {
    asm("mma.sync.aligned.m16n8k16.row.col.f32.bf16.bf16.f32 "
        "{%0,%1,%2,%3}, {%4,%5,%6,%7}, {%8,%9}, {%0,%1,%2,%3};"
        : "+f"(c[0]), "+f"(c[1]), "+f"(c[2]), "+f"(c[3])
        : "r"(a[0]), "r"(a[1]), "r"(a[2]), "r"(a[3]), "r"(b[0]), "r"(b[1]));
}

// tf32 helpers for the MLP (R12-proven)
static __device__ __forceinline__ void tf32_split(float x, uint32_t& hi, uint32_t& lo) {
    uint32_t h;
    asm("cvt.rna.tf32.f32 %0, %1;" : "=r"(h) : "f"(x));
    float l = x - __uint_as_float(h);
    uint32_t lw;
    asm("cvt.rna.tf32.f32 %0, %1;" : "=r"(lw) : "f"(l));
    hi = h; lo = lw;
}
static __device__ __forceinline__ void mma_tf32(float c[4], const uint32_t a[4], const uint32_t b[2]) {
    asm("mma.sync.aligned.m16n8k8.row.col.f32.tf32.tf32.f32 "
        "{%0,%1,%2,%3}, {%4,%5,%6,%7}, {%8,%9}, {%0,%1,%2,%3};"
        : "+f"(c[0]), "+f"(c[1]), "+f"(c[2]), "+f"(c[3])
        : "r"(a[0]), "r"(a[1]), "r"(a[2]), "r"(a[3]), "r"(b[0]), "r"(b[1]));
}

// ---------------------------------------------------------------------------
// Setup: G = A A^T + 1e-6 I, Gauss-Jordan inverse, Q = G^{-1} A, then pack
// A^T and Q into bf16-split fragment-ready arrays.
// ---------------------------------------------------------------------------
__global__ void setup_kernel(const float* __restrict__ A)
{
    __shared__ float G[32][65];
    __shared__ float fcol[32];
    const int t = threadIdx.x;
    const int i = t >> 5;
    const int j = t & 31;

    float s = 0.f;
    for (int k = 0; k < DIMV; k++)
        s += A[i * DIMV + k] * A[j * DIMV + k];
    G[i][j]      = s + (i == j ? 1e-6f : 0.f);
    G[i][j + 32] = (i == j) ? 1.f : 0.f;
    __syncthreads();

    for (int k = 0; k < 32; k++) {
        if (j == 0) fcol[i] = G[i][k];
        __syncthreads();
        if (i == k) {
            float inv = 1.f / fcol[k];
            G[k][j]      *= inv;
            G[k][j + 32] *= inv;
        }
        __syncthreads();
        if (i != k) {
            float f = fcol[i];
            G[i][j]      -= f * G[k][j];
            G[i][j + 32] -= f * G[k][j + 32];
        }
        __syncthreads();
    }

    for (int r = 0; r < 8; r++) {
        int idx = t + r * 1024;
        int m = idx >> 8;
        int d = idx & 255;
        float acc = 0.f;
        for (int k = 0; k < 32; k++)
            acc += G[m][32 + k] * A[k * DIMV + d];
        g_Q[m * DIMV + d] = acc;
    }
    __syncthreads();

    // Pack B1 = A^T: B1pack[d2][m] = bf16x2(A[m][2d2], A[m][2d2+1])
    // Pack Q2: Q2pack[m2][d] = bf16x2(Q[2m2][d], Q[2m2+1][d])
    for (int l = 0; l < 4; l++) {
        int idx = t + l * 1024;    // 0..4095
        {
            int d2 = idx >> 5, m = idx & 31;
            float a0 = A[m * DIMV + 2 * d2];
            float a1 = A[m * DIMV + 2 * d2 + 1];
            uint32_t hi, lo; bf16_split_pack(a0, a1, hi, lo);
            g_B1hi[d2 * B1_STRIDE + m] = hi;
            g_B1lo[d2 * B1_STRIDE + m] = lo;
        }
        {
            int m2 = idx >> 8, d = idx & 255;
            float q0 = g_Q[(2 * m2) * DIMV + d];
            float q1 = g_Q[(2 * m2 + 1) * DIMV + d];
            uint32_t hi, lo; bf16_split_pack(q0, q1, hi, lo);
            g_Q2hi[m2 * Q2_STRIDE + d] = hi;
            g_Q2lo[m2 * Q2_STRIDE + d] = lo;
        }
    }
}

// ---------------------------------------------------------------------------
// 3xTF32 tensor-core MLP GEMM (R12-proven, 18.6us/layer)
// ---------------------------------------------------------------------------
template<bool RELU>
__global__ __launch_bounds__(256)
void gemm_tf32_kernel(const float* __restrict__ X, const float* __restrict__ W,
                      const float* __restrict__ bias, float* __restrict__ Y,
                      int N, int K)
{
    __shared__ float Xs[64][36];
    __shared__ float Ws[32][72];
    const int t    = threadIdx.x;
    const int lane = t & 31;
    const int wid  = t >> 5;
    const int row0 = blockIdx.y * 64;
    const int col0 = blockIdx.x * 64;
    const int wm = (wid & 1) * 32;
    const int wn = (wid >> 1) * 16;
    const int lr = lane >> 2;
    const int lc = lane & 3;

    float c[2][2][4];
#pragma unroll
    for (int mt = 0; mt < 2; mt++)
#pragma unroll
        for (int nt = 0; nt < 2; nt++)
#pragma unroll
            for (int q = 0; q < 4; q++) c[mt][nt][q] = 0.f;

    const int nkt = (K + 31) / 32;
    for (int kt = 0; kt < nkt; kt++) {
        const int kbase = kt * 32;
#pragma unroll
        for (int l = 0; l < 2; l++) {
            int idx = t + l * 256;
            int r = idx >> 3;
            int q = idx & 7;
            int kk = kbase + q * 4;
            float4 v = make_float4(0.f, 0.f, 0.f, 0.f);
            if (kk + 4 <= K) v = *(const float4*)&X[(size_t)(row0 + r) * K + kk];
            *(float4*)&Xs[r][q * 4] = v;
        }
#pragma unroll
        for (int l = 0; l < 2; l++) {
            int idx = t + l * 256;
            int k = idx >> 4;
            int cq = idx & 15;
            int gk = kbase + k;
            int gc = col0 + cq * 4;
            float4 v = make_float4(0.f, 0.f, 0.f, 0.f);
            if (gk < K && gc + 4 <= N) v = *(const float4*)&W[(size_t)gk * N + gc];
            *(float4*)&Ws[k][cq * 4] = v;
        }
        __syncthreads();

#pragma unroll
        for (int ks = 0; ks < 4; ks++) {
            const int k0 = ks * 8;
            uint32_t ahi[2][4], alo[2][4];
#pragma unroll
            for (int mt = 0; mt < 2; mt++) {
                int rb = wm + mt * 16;
                float a0 = Xs[rb + lr    ][k0 + lc    ];
                float a1 = Xs[rb + lr + 8][k0 + lc    ];
                float a2 = Xs[rb + lr    ][k0 + lc + 4];
                float a3 = Xs[rb + lr + 8][k0 + lc + 4];
                tf32_split(a0, ahi[mt][0], alo[mt][0]);
                tf32_split(a1, ahi[mt][1], alo[mt][1]);
                tf32_split(a2, ahi[mt][2], alo[mt][2]);
                tf32_split(a3, ahi[mt][3], alo[mt][3]);
            }
            uint32_t bhi[2][2], blo[2][2];
#pragma unroll
            for (int nt = 0; nt < 2; nt++) {
                int cb = wn + nt * 8;
                float b0 = Ws[k0 + lc    ][cb + lr];
                float b1 = Ws[k0 + lc + 4][cb + lr];
                tf32_split(b0, bhi[nt][0], blo[nt][0]);
                tf32_split(b1, bhi[nt][1], blo[nt][1]);
            }
#pragma unroll
            for (int mt = 0; mt < 2; mt++)
#pragma unroll
                for (int nt = 0; nt < 2; nt++) {
                    mma_tf32(c[mt][nt], ahi[mt], bhi[nt]);
                    mma_tf32(c[mt][nt], ahi[mt], blo[nt]);
                    mma_tf32(c[mt][nt], alo[mt], bhi[nt]);
                }
        }
        __syncthreads();
    }

#pragma unroll
    for (int mt = 0; mt < 2; mt++) {
#pragma unroll
        for (int nt = 0; nt < 2; nt++) {
            int row = row0 + wm + mt * 16 + lr;
            int col = col0 + wn + nt * 8 + 2 * lc;
            if (col < N) {
                float bv0 = bias[col], bv1 = bias[col + 1];
                float v0 = c[mt][nt][0] + bv0;
                float v1 = c[mt][nt][1] + bv1;
                float v2 = c[mt][nt][2] + bv0;
                float v3 = c[mt][nt][3] + bv1;
                if (RELU) {
                    v0 = fmaxf(v0, 0.f); v1 = fmaxf(v1, 0.f);
                    v2 = fmaxf(v2, 0.f); v3 = fmaxf(v3, 0.f);
                }
                Y[(size_t)row * N + col]           = v0;
                Y[(size_t)row * N + col + 1]       = v1;
                Y[(size_t)(row + 8) * N + col]     = v2;
                Y[(size_t)(row + 8) * N + col + 1] = v3;
            }
        }
    }
}

// ---------------------------------------------------------------------------
// Tensor-core DR iteration. Warp = 16 rows (one task). 128 CTAs x 64 thr.
// z lives in C-fragment layout [32 ntiles][4]; C-layout n == A-layout k, so
// z -> GEMM1 A-frags and r -> GEMM2 A-frags are thread-local conversions.
// bf16 3-term split (hi*hi + hi*lo + lo*hi) ~ 2^-18 product accuracy.
// ---------------------------------------------------------------------------
#define DR_TOL 5e-3f

__global__ __launch_bounds__(64)
void iter_mma_kernel(const float* __restrict__ bmat,
                     const int*   __restrict__ n_iter_ptr,
                     float* __restrict__ out)
{
    extern __shared__ uint32_t sm[];
    uint32_t* sB1hi = sm;                       // 5120
    uint32_t* sB1lo = sm + B1_WORDS;            // 5120
    uint32_t* sQ2hi = sm + 2 * B1_WORDS;        // 4224
    uint32_t* sQ2lo = sm + 2 * B1_WORDS + Q2_WORDS;
    const int t = threadIdx.x;
    for (int i = t; i < B1_WORDS; i += 64) { sB1hi[i] = g_B1hi[i]; sB1lo[i] = g_B1lo[i]; }
    for (int i = t; i < Q2_WORDS; i += 64) { sQ2hi[i] = g_Q2hi[i]; sQ2lo[i] = g_Q2lo[i]; }
    __syncthreads();

    const int wid  = t >> 5;
    const int lane = t & 31;
    const int g  = lane >> 2;    // 0..7
    const int tg = lane & 3;     // 0..3
    const int task = blockIdx.x * 2 + wid;     // 0..255
    const int rowbase = task * 16;
    const int r0g = rowbase + g;
    const int r8g = rowbase + g + 8;

    // z in C2-fragment layout: z[nt] = {(g,8nt+2tg),(g,+1),(g+8,8nt+2tg),(g+8,+1)}
    float z[32][4];
#pragma unroll
    for (int nt = 0; nt < 32; nt++) {
        float2 v0 = *(const float2*)&g_Y[(size_t)r0g * DIMV + 8 * nt + 2 * tg];
        float2 v1 = *(const float2*)&g_Y[(size_t)r8g * DIMV + 8 * nt + 2 * tg];
        z[nt][0] = v0.x; z[nt][1] = v0.y; z[nt][2] = v1.x; z[nt][3] = v1.y;
    }
    // b in C1-fragment layout
    float bv[4][4];
#pragma unroll
    for (int mt = 0; mt < 4; mt++) {
        float2 v0 = *(const float2*)&bmat[(size_t)r0g * MM + 8 * mt + 2 * tg];
        float2 v1 = *(const float2*)&bmat[(size_t)r8g * MM + 8 * mt + 2 * tg];
        bv[mt][0] = v0.x; bv[mt][1] = v0.y; bv[mt][2] = v1.x; bv[mt][3] = v1.y;
    }

    const int niter = *n_iter_ptr;
    const unsigned FULL = 0xffffffffu;
    bool last = (niter <= 0);
    int done = 0;

    for (;;) {
        // ---- GEMM1: r = z A^T  (C1 frags, 4 m-tiles) ----
        float c1[4][4];
#pragma unroll
        for (int mt = 0; mt < 4; mt++)
#pragma unroll
            for (int q = 0; q < 4; q++) c1[mt][q] = 0.f;

#pragma unroll
        for (int ks = 0; ks < 16; ks++) {
            uint32_t ahi[4], alo[4];
            bf16_split_pack(z[2*ks  ][0], z[2*ks  ][1], ahi[0], alo[0]);
            bf16_split_pack(z[2*ks  ][2], z[2*ks  ][3], ahi[1], alo[1]);
            bf16_split_pack(z[2*ks+1][0], z[2*ks+1][1], ahi[2], alo[2]);
            bf16_split_pack(z[2*ks+1][2], z[2*ks+1][3], ahi[3], alo[3]);
#pragma unroll
            for (int mt = 0; mt < 4; mt++) {
                const int i0 = (8 * ks + tg) * B1_STRIDE + 8 * mt + g;
                const int i1 = (8 * ks + 4 + tg) * B1_STRIDE + 8 * mt + g;
                uint32_t bh[2] = { sB1hi[i0], sB1hi[i1] };
                uint32_t bl[2] = { sB1lo[i0], sB1lo[i1] };
                mma_bf16(c1[mt], ahi, bh);
                mma_bf16(c1[mt], ahi, bl);
                mma_bf16(c1[mt], alo, bh);
            }
        }

        // ---- r = c1 - b, split into GEMM2 A-frags ----
        uint32_t rhi[2][4], rlo[2][4];
#pragma unroll
        for (int ks2 = 0; ks2 < 2; ks2++) {
            float f0 = c1[2*ks2  ][0] - bv[2*ks2  ][0];
            float f1 = c1[2*ks2  ][1] - bv[2*ks2  ][1];
            float f2 = c1[2*ks2  ][2] - bv[2*ks2  ][2];
            float f3 = c1[2*ks2  ][3] - bv[2*ks2  ][3];
            float f4 = c1[2*ks2+1][0] - bv[2*ks2+1][0];
            float f5 = c1[2*ks2+1][1] - bv[2*ks2+1][1];
            float f6 = c1[2*ks2+1][2] - bv[2*ks2+1][2];
            float f7 = c1[2*ks2+1][3] - bv[2*ks2+1][3];
            bf16_split_pack(f0, f1, rhi[ks2][0], rlo[ks2][0]);
            bf16_split_pack(f2, f3, rhi[ks2][1], rlo[ks2][1]);
            bf16_split_pack(f4, f5, rhi[ks2][2], rlo[ks2][2]);
            bf16_split_pack(f6, f7, rhi[ks2][3], rlo[ks2][3]);
        }

        // ---- GEMM2 per n-tile: u = z - r Q ; update z or store ----
        float dmax = 0.f;
#pragma unroll
        for (int nt = 0; nt < 32; nt++) {
            float c2[4] = {0.f, 0.f, 0.f, 0.f};
#pragma unroll
            for (int ks2 = 0; ks2 < 2; ks2++) {
                const int i0 = (8 * ks2 + tg) * Q2_STRIDE + 8 * nt + g;
                const int i1 = (8 * ks2 + 4 + tg) * Q2_STRIDE + 8 * nt + g;
                uint32_t bh[2] = { sQ2hi[i0], sQ2hi[i1] };
                uint32_t bl[2] = { sQ2lo[i0], sQ2lo[i1] };
                mma_bf16(c2, rhi[ks2], bh);
                mma_bf16(c2, rhi[ks2], bl);
                mma_bf16(c2, rlo[ks2], bh);
            }
            if (last) {
                *(float2*)&out[(size_t)r0g * DIMV + 8 * nt + 2 * tg] =
                    make_float2(z[nt][0] - c2[0], z[nt][1] - c2[1]);
                *(float2*)&out[(size_t)r8g * DIMV + 8 * nt + 2 * tg] =
                    make_float2(z[nt][2] - c2[2], z[nt][3] - c2[3]);
            } else {
#pragma unroll
                for (int q = 0; q < 4; q++) {
                    float u = z[nt][q] - c2[q];
                    float v = fminf(fmaxf(2.f * u - z[nt][q], 0.f), 1.f);
                    float d = v - u;
                    z[nt][q] = fmaf(1.7f, d, z[nt][q]);
                    dmax = fmaxf(dmax, fabsf(d));
                }
            }
        }

        if (last) break;
        done++;
        if (done >= niter || __all_sync(FULL, dmax < DR_TOL)) last = true;
    }
}

// ---------------------------------------------------------------------------
// Launch
// ---------------------------------------------------------------------------
extern "C" void kernel_launch(void* const* d_in, const int* in_sizes, int n_in,
                              void* d_out, int out_size)
{
    const float* x   = (const float*)d_in[0];
    const float* b   = (const float*)d_in[1];
    const float* W1  = (const float*)d_in[2];
    const float* b1  = (const float*)d_in[3];
    const float* W2  = (const float*)d_in[4];
    const float* b2  = (const float*)d_in[5];
    const float* W3  = (const float*)d_in[6];
    const float* b3  = (const float*)d_in[7];
    const float* A   = (const float*)d_in[8];
    const int* n_it  = (const int*)d_in[10];
    float* out = (float*)d_out;

    setup_kernel<<<1, 1024>>>(A);

    float* h1; cudaGetSymbolAddress((void**)&h1, g_H1);
    float* h2; cudaGetSymbolAddress((void**)&h2, g_H2);
    float* y;  cudaGetSymbolAddress((void**)&y,  g_Y);

    gemm_tf32_kernel<true ><<<dim3((HID  + 63) / 64, BB / 64), 256>>>(x,  W1, b1, h1, HID,  D_IN);
    gemm_tf32_kernel<true ><<<dim3((HID  + 63) / 64, BB / 64), 256>>>(h1, W2, b2, h2, HID,  HID);
    gemm_tf32_kernel<false><<<dim3((DIMV + 63) / 64, BB / 64), 256>>>(h2, W3, b3, y,  DIMV, HID);

    // Tensor-core iteration: 128 CTAs x 64 thr, warp = 16 rows.
    const int smem_bytes = (2 * B1_WORDS + 2 * Q2_WORDS) * 4;   // 74752
    cudaFuncSetAttribute(iter_mma_kernel, cudaFuncAttributeMaxDynamicSharedMemorySize, smem_bytes);
    iter_mma_kernel<<<BB / 32, 64, smem_bytes>>>(b, n_it, out);
}

// round 14
// speedup vs baseline: 1.3886x; 1.3886x over previous
#include <cuda_runtime.h>
#include <cstdint>
#include <cstring>

// Problem constants
#define BB     4096
#define D_IN   128
#define HID    200
#define DIMV   256
#define MM     32

#define B1_STRIDE 40    // pad: bank = 8tg+g (+8mt) -> conflict-free
#define Q2_STRIDE 264   // pad: bank = 8tg+g+8nt   -> conflict-free
#define B1_WORDS (128 * B1_STRIDE)   // 5120
#define Q2_WORDS (16 * Q2_STRIDE)    // 4224
#define EXCH_WORDS (2 * 2 * 32 * 16) // c1 exchange: [pair][half][lane][16]
#define SM_WORDS (2 * B1_WORDS + 2 * Q2_WORDS + EXCH_WORDS + 8)

// Scratch (device globals — no allocation allowed)
__device__ float g_H1[BB * HID];
__device__ float g_H2[BB * HID];
__device__ float g_Y [BB * DIMV];
__device__ float g_Q [MM * DIMV];
__device__ uint32_t g_B1hi[B1_WORDS];   // A^T packed bf16x2 (hi), fragment order
__device__ uint32_t g_B1lo[B1_WORDS];
__device__ uint32_t g_Q2hi[Q2_WORDS];   // Q packed bf16x2 (hi)
__device__ uint32_t g_Q2lo[Q2_WORDS];

// ---------------------------------------------------------------------------
// bf16 split-pack: x = hi + lo, packed bf16x2 {x0 low half, x1 high half}.
// ---------------------------------------------------------------------------
static __device__ __forceinline__ void bf16_split_pack(float x0, float x1,
                                                       uint32_t& hi, uint32_t& lo) {
    uint32_t h;
    asm("cvt.rn.bf16x2.f32 %0, %1, %2;" : "=r"(h) : "f"(x1), "f"(x0));
    float h0 = __uint_as_float(h << 16);
    float h1 = __uint_as_float(h & 0xFFFF0000u);
    float r0 = x0 - h0;
    float r1 = x1 - h1;
    uint32_t l;
    asm("cvt.rn.bf16x2.f32 %0, %1, %2;" : "=r"(l) : "f"(r1), "f"(r0));
    hi = h; lo = l;
}

static __device__ __forceinline__ void mma_bf16(float c[4], const uint32_t a[4],
                                                const uint32_t b[2]) {
    asm("mma.sync.aligned.m16n8k16.row.col.f32.bf16.bf16.f32 "
        "{%0,%1,%2,%3}, {%4,%5,%6,%7}, {%8,%9}, {%0,%1,%2,%3};"
        : "+f"(c[0]), "+f"(c[1]), "+f"(c[2]), "+f"(c[3])
        : "r"(a[0]), "r"(a[1]), "r"(a[2]), "r"(a[3]), "r"(b[0]), "r"(b[1]));
}

// tf32 helpers for the MLP (R12-proven)
static __device__ __forceinline__ void tf32_split(float x, uint32_t& hi, uint32_t& lo) {
    uint32_t h;
    asm("cvt.rna.tf32.f32 %0, %1;" : "=r"(h) : "f"(x));
    float l = x - __uint_as_float(h);
    uint32_t lw;
    asm("cvt.rna.tf32.f32 %0, %1;" : "=r"(lw) : "f"(l));
    hi = h; lo = lw;
}
static __device__ __forceinline__ void mma_tf32(float c[4], const uint32_t a[4], const uint32_t b[2]) {
    asm("mma.sync.aligned.m16n8k8.row.col.f32.tf32.tf32.f32 "
        "{%0,%1,%2,%3}, {%4,%5,%6,%7}, {%8,%9}, {%0,%1,%2,%3};"
        : "+f"(c[0]), "+f"(c[1]), "+f"(c[2]), "+f"(c[3])
        : "r"(a[0]), "r"(a[1]), "r"(a[2]), "r"(a[3]), "r"(b[0]), "r"(b[1]));
}

// ---------------------------------------------------------------------------
// Setup: G = A A^T + 1e-6 I, Gauss-Jordan inverse, Q = G^{-1} A, then pack
// A^T and Q into bf16-split fragment-ready arrays.
// ---------------------------------------------------------------------------
__global__ void setup_kernel(const float* __restrict__ A)
{
    __shared__ float G[32][65];
    __shared__ float fcol[32];
    const int t = threadIdx.x;
    const int i = t >> 5;
    const int j = t & 31;

    float s = 0.f;
    for (int k = 0; k < DIMV; k++)
        s += A[i * DIMV + k] * A[j * DIMV + k];
    G[i][j]      = s + (i == j ? 1e-6f : 0.f);
    G[i][j + 32] = (i == j) ? 1.f : 0.f;
    __syncthreads();

    for (int k = 0; k < 32; k++) {
        if (j == 0) fcol[i] = G[i][k];
        __syncthreads();
        if (i == k) {
            float inv = 1.f / fcol[k];
            G[k][j]      *= inv;
            G[k][j + 32] *= inv;
        }
        __syncthreads();
        if (i != k) {
            float f = fcol[i];
            G[i][j]      -= f * G[k][j];
            G[i][j + 32] -= f * G[k][j + 32];
        }
        __syncthreads();
    }

    for (int r = 0; r < 8; r++) {
        int idx = t + r * 1024;
        int m = idx >> 8;
        int d = idx & 255;
        float acc = 0.f;
        for (int k = 0; k < 32; k++)
            acc += G[m][32 + k] * A[k * DIMV + d];
        g_Q[m * DIMV + d] = acc;
    }
    __syncthreads();

    // Pack B1 = A^T: B1pack[d2][m] = bf16x2(A[m][2d2], A[m][2d2+1])
    // Pack Q2: Q2pack[m2][d] = bf16x2(Q[2m2][d], Q[2m2+1][d])
    for (int l = 0; l < 4; l++) {
        int idx = t + l * 1024;    // 0..4095
        {
            int d2 = idx >> 5, m = idx & 31;
            float a0 = A[m * DIMV + 2 * d2];
            float a1 = A[m * DIMV + 2 * d2 + 1];
            uint32_t hi, lo; bf16_split_pack(a0, a1, hi, lo);
            g_B1hi[d2 * B1_STRIDE + m] = hi;
            g_B1lo[d2 * B1_STRIDE + m] = lo;
        }
        {
            int m2 = idx >> 8, d = idx & 255;
            float q0 = g_Q[(2 * m2) * DIMV + d];
            float q1 = g_Q[(2 * m2 + 1) * DIMV + d];
            uint32_t hi, lo; bf16_split_pack(q0, q1, hi, lo);
            g_Q2hi[m2 * Q2_STRIDE + d] = hi;
            g_Q2lo[m2 * Q2_STRIDE + d] = lo;
        }
    }
}

// ---------------------------------------------------------------------------
// 3xTF32 tensor-core MLP GEMM (R12-proven, 18.6us/layer)
// ---------------------------------------------------------------------------
template<bool RELU>
__global__ __launch_bounds__(256)
void gemm_tf32_kernel(const float* __restrict__ X, const float* __restrict__ W,
                      const float* __restrict__ bias, float* __restrict__ Y,
                      int N, int K)
{
    __shared__ float Xs[64][36];
    __shared__ float Ws[32][72];
    const int t    = threadIdx.x;
    const int lane = t & 31;
    const int wid  = t >> 5;
    const int row0 = blockIdx.y * 64;
    const int col0 = blockIdx.x * 64;
    const int wm = (wid & 1) * 32;
    const int wn = (wid >> 1) * 16;
    const int lr = lane >> 2;
    const int lc = lane & 3;

    float c[2][2][4];
#pragma unroll
    for (int mt = 0; mt < 2; mt++)
#pragma unroll
        for (int nt = 0; nt < 2; nt++)
#pragma unroll
            for (int q = 0; q < 4; q++) c[mt][nt][q] = 0.f;

    const int nkt = (K + 31) / 32;
    for (int kt = 0; kt < nkt; kt++) {
        const int kbase = kt * 32;
#pragma unroll
        for (int l = 0; l < 2; l++) {
            int idx = t + l * 256;
            int r = idx >> 3;
            int q = idx & 7;
            int kk = kbase + q * 4;
            float4 v = make_float4(0.f, 0.f, 0.f, 0.f);
            if (kk + 4 <= K) v = *(const float4*)&X[(size_t)(row0 + r) * K + kk];
            *(float4*)&Xs[r][q * 4] = v;
        }
#pragma unroll
        for (int l = 0; l < 2; l++) {
            int idx = t + l * 256;
            int k = idx >> 4;
            int cq = idx & 15;
            int gk = kbase + k;
            int gc = col0 + cq * 4;
            float4 v = make_float4(0.f, 0.f, 0.f, 0.f);
            if (gk < K && gc + 4 <= N) v = *(const float4*)&W[(size_t)gk * N + gc];
            *(float4*)&Ws[k][cq * 4] = v;
        }
        __syncthreads();

#pragma unroll
        for (int ks = 0; ks < 4; ks++) {
            const int k0 = ks * 8;
            uint32_t ahi[2][4], alo[2][4];
#pragma unroll
            for (int mt = 0; mt < 2; mt++) {
                int rb = wm + mt * 16;
                float a0 = Xs[rb + lr    ][k0 + lc    ];
                float a1 = Xs[rb + lr + 8][k0 + lc    ];
                float a2 = Xs[rb + lr    ][k0 + lc + 4];
                float a3 = Xs[rb + lr + 8][k0 + lc + 4];
                tf32_split(a0, ahi[mt][0], alo[mt][0]);
                tf32_split(a1, ahi[mt][1], alo[mt][1]);
                tf32_split(a2, ahi[mt][2], alo[mt][2]);
                tf32_split(a3, ahi[mt][3], alo[mt][3]);
            }
            uint32_t bhi[2][2], blo[2][2];
#pragma unroll
            for (int nt = 0; nt < 2; nt++) {
                int cb = wn + nt * 8;
                float b0 = Ws[k0 + lc    ][cb + lr];
                float b1 = Ws[k0 + lc + 4][cb + lr];
                tf32_split(b0, bhi[nt][0], blo[nt][0]);
                tf32_split(b1, bhi[nt][1], blo[nt][1]);
            }
#pragma unroll
            for (int mt = 0; mt < 2; mt++)
#pragma unroll
                for (int nt = 0; nt < 2; nt++) {
                    mma_tf32(c[mt][nt], ahi[mt], bhi[nt]);
                    mma_tf32(c[mt][nt], ahi[mt], blo[nt]);
                    mma_tf32(c[mt][nt], alo[mt], bhi[nt]);
                }
        }
        __syncthreads();
    }

#pragma unroll
    for (int mt = 0; mt < 2; mt++) {
#pragma unroll
        for (int nt = 0; nt < 2; nt++) {
            int row = row0 + wm + mt * 16 + lr;
            int col = col0 + wn + nt * 8 + 2 * lc;
            if (col < N) {
                float bv0 = bias[col], bv1 = bias[col + 1];
                float v0 = c[mt][nt][0] + bv0;
                float v1 = c[mt][nt][1] + bv1;
                float v2 = c[mt][nt][2] + bv0;
                float v3 = c[mt][nt][3] + bv1;
                if (RELU) {
                    v0 = fmaxf(v0, 0.f); v1 = fmaxf(v1, 0.f);
                    v2 = fmaxf(v2, 0.f); v3 = fmaxf(v3, 0.f);
                }
                Y[(size_t)row * N + col]           = v0;
                Y[(size_t)row * N + col + 1]       = v1;
                Y[(size_t)(row + 8) * N + col]     = v2;
                Y[(size_t)(row + 8) * N + col + 1] = v3;
            }
        }
    }
}

// ---------------------------------------------------------------------------
// Cooperative-pair tensor-core DR iteration.
// CTA = 128 thr = 4 warps = 2 tasks; warp pair (wHalf 0/1) splits one 16-row
// task: warp h owns z n-tiles [16h,16h+16) == GEMM1 k-chunk [8h,8h+8)
// (nt = 2ks alignment), partial C1 summed via smem, GEMM2 over own nt-half.
// wid%4 -> all 4 SMSPs active. 3 barriers/pass. Split terms use separate
// accumulators (12 independent MMA chains) to hide HMMA latency at 1 warp/SMSP.
// ---------------------------------------------------------------------------
#define DR_TOL 5e-3f

__global__ __launch_bounds__(128)
void iter_mma_kernel(const float* __restrict__ bmat,
                     const int*   __restrict__ n_iter_ptr,
                     float* __restrict__ out)
{
    extern __shared__ uint32_t sm[];
    uint32_t* sB1hi = sm;
    uint32_t* sB1lo = sm + B1_WORDS;
    uint32_t* sQ2hi = sm + 2 * B1_WORDS;
    uint32_t* sQ2lo = sm + 2 * B1_WORDS + Q2_WORDS;
    float*    sExch = (float*)(sm + 2 * B1_WORDS + 2 * Q2_WORDS);   // [2][2][32][16]
    volatile int* sFlag = (volatile int*)(sm + 2 * B1_WORDS + 2 * Q2_WORDS + EXCH_WORDS);
    // sFlag[0..1] = task done; sFlag[2..5] = votes [pair*2 + half]

    const int t = threadIdx.x;
    for (int i = t; i < B1_WORDS; i += 128) { sB1hi[i] = g_B1hi[i]; sB1lo[i] = g_B1lo[i]; }
    for (int i = t; i < Q2_WORDS; i += 128) { sQ2hi[i] = g_Q2hi[i]; sQ2lo[i] = g_Q2lo[i]; }
    if (t < 6) ((volatile int*)sFlag)[t] = 0;
    __syncthreads();

    const int wid   = t >> 5;
    const int lane  = t & 31;
    const int pair  = wid >> 1;       // 0..1: which task
    const int wh    = wid & 1;        // 0..1: which half of the task
    const int g     = lane >> 2;      // 0..7
    const int tg    = lane & 3;       // 0..3
    const int task  = blockIdx.x * 2 + pair;          // 0..255
    const int rowbase = task * 16;
    const int r0g = rowbase + g;
    const int r8g = rowbase + g + 8;

    float* myExch = &sExch[((pair * 2 + wh) * 32 + lane) * 16];
    float* otExch = &sExch[((pair * 2 + (wh ^ 1)) * 32 + lane) * 16];

    // z: this warp's 16 n-tiles (global nt = 16*wh + j); C2-fragment layout.
    float z[16][4];
#pragma unroll
    for (int j = 0; j < 16; j++) {
        const int ntg = 16 * wh + j;
        float2 v0 = *(const float2*)&g_Y[(size_t)r0g * DIMV + 8 * ntg + 2 * tg];
        float2 v1 = *(const float2*)&g_Y[(size_t)r8g * DIMV + 8 * ntg + 2 * tg];
        z[j][0] = v0.x; z[j][1] = v0.y; z[j][2] = v1.x; z[j][3] = v1.y;
    }
    // b in C1-fragment layout (full; both halves need it for r)
    float bv[4][4];
#pragma unroll
    for (int mt = 0; mt < 4; mt++) {
        float2 v0 = *(const float2*)&bmat[(size_t)r0g * MM + 8 * mt + 2 * tg];
        float2 v1 = *(const float2*)&bmat[(size_t)r8g * MM + 8 * mt + 2 * tg];
        bv[mt][0] = v0.x; bv[mt][1] = v0.y; bv[mt][2] = v1.x; bv[mt][3] = v1.y;
    }

    const int niter = *n_iter_ptr;
    const unsigned FULL = 0xffffffffu;
    bool last = (niter <= 0);
    bool myDone = false;
    int done = 0;

    for (;;) {
        // ---- Phase 1: partial GEMM1 over this warp's k-half ----
        if (!myDone) {
            float chh[4][4], chl[4][4], clh[4][4];
#pragma unroll
            for (int mt = 0; mt < 4; mt++)
#pragma unroll
                for (int q = 0; q < 4; q++) { chh[mt][q] = 0.f; chl[mt][q] = 0.f; clh[mt][q] = 0.f; }

#pragma unroll
            for (int ksl = 0; ksl < 8; ksl++) {
                const int ks = 8 * wh + ksl;
                uint32_t ahi[4], alo[4];
                bf16_split_pack(z[2*ksl  ][0], z[2*ksl  ][1], ahi[0], alo[0]);
                bf16_split_pack(z[2*ksl  ][2], z[2*ksl  ][3], ahi[1], alo[1]);
                bf16_split_pack(z[2*ksl+1][0], z[2*ksl+1][1], ahi[2], alo[2]);
                bf16_split_pack(z[2*ksl+1][2], z[2*ksl+1][3], ahi[3], alo[3]);
#pragma unroll
                for (int mt = 0; mt < 4; mt++) {
                    const int i0 = (8 * ks + tg) * B1_STRIDE + 8 * mt + g;
                    const int i1 = (8 * ks + 4 + tg) * B1_STRIDE + 8 * mt + g;
                    uint32_t bh[2] = { sB1hi[i0], sB1hi[i1] };
                    uint32_t bl[2] = { sB1lo[i0], sB1lo[i1] };
                    mma_bf16(chh[mt], ahi, bh);
                    mma_bf16(chl[mt], ahi, bl);
                    mma_bf16(clh[mt], alo, bh);
                }
            }
#pragma unroll
            for (int mt = 0; mt < 4; mt++)
#pragma unroll
                for (int q = 0; q < 4; q++)
                    myExch[mt * 4 + q] = chh[mt][q] + chl[mt][q] + clh[mt][q];
        }
        __syncthreads();   // barrier 1

        // ---- Phase 2: sum partials, r, GEMM2 over own nt-half ----
        if (!myDone) {
            float c1[4][4];
#pragma unroll
            for (int mt = 0; mt < 4; mt++)
#pragma unroll
                for (int q = 0; q < 4; q++)
                    c1[mt][q] = myExch[mt * 4 + q] + otExch[mt * 4 + q];

            uint32_t rhi[2][4], rlo[2][4];
#pragma unroll
            for (int ks2 = 0; ks2 < 2; ks2++) {
                float f0 = c1[2*ks2  ][0] - bv[2*ks2  ][0];
                float f1 = c1[2*ks2  ][1] - bv[2*ks2  ][1];
                float f2 = c1[2*ks2  ][2] - bv[2*ks2  ][2];
                float f3 = c1[2*ks2  ][3] - bv[2*ks2  ][3];
                float f4 = c1[2*ks2+1][0] - bv[2*ks2+1][0];
                float f5 = c1[2*ks2+1][1] - bv[2*ks2+1][1];
                float f6 = c1[2*ks2+1][2] - bv[2*ks2+1][2];
                float f7 = c1[2*ks2+1][3] - bv[2*ks2+1][3];
                bf16_split_pack(f0, f1, rhi[ks2][0], rlo[ks2][0]);
                bf16_split_pack(f2, f3, rhi[ks2][1], rlo[ks2][1]);
                bf16_split_pack(f4, f5, rhi[ks2][2], rlo[ks2][2]);
                bf16_split_pack(f6, f7, rhi[ks2][3], rlo[ks2][3]);
            }

            float dmax = 0.f;
#pragma unroll
            for (int j = 0; j < 16; j++) {
                const int ntg = 16 * wh + j;
                float chh2[4] = {0.f,0.f,0.f,0.f}, chl2[4] = {0.f,0.f,0.f,0.f}, clh2[4] = {0.f,0.f,0.f,0.f};
#pragma unroll
                for (int ks2 = 0; ks2 < 2; ks2++) {
                    const int i0 = (8 * ks2 + tg) * Q2_STRIDE + 8 * ntg + g;
                    const int i1 = (8 * ks2 + 4 + tg) * Q2_STRIDE + 8 * ntg + g;
                    uint32_t bh[2] = { sQ2hi[i0], sQ2hi[i1] };
                    uint32_t bl[2] = { sQ2lo[i0], sQ2lo[i1] };
                    mma_bf16(chh2, rhi[ks2], bh);
                    mma_bf16(chl2, rhi[ks2], bl);
                    mma_bf16(clh2, rlo[ks2], bh);
                }
                float c2[4];
#pragma unroll
                for (int q = 0; q < 4; q++) c2[q] = chh2[q] + chl2[q] + clh2[q];

                if (last) {
                    *(float2*)&out[(size_t)r0g * DIMV + 8 * ntg + 2 * tg] =
                        make_float2(z[j][0] - c2[0], z[j][1] - c2[1]);
                    *(float2*)&out[(size_t)r8g * DIMV + 8 * ntg + 2 * tg] =
                        make_float2(z[j][2] - c2[2], z[j][3] - c2[3]);
                } else {
#pragma unroll
                    for (int q = 0; q < 4; q++) {
                        float u = z[j][q] - c2[q];
                        float v = fminf(fmaxf(2.f * u - z[j][q], 0.f), 1.f);
                        float d = v - u;
                        z[j][q] = fmaf(1.7f, d, z[j][q]);
                        dmax = fmaxf(dmax, fabsf(d));
                    }
                }
            }
            if (!last) {
                int conv = __all_sync(FULL, dmax < DR_TOL) ? 1 : 0;
                if (lane == 0) ((volatile int*)sFlag)[2 + pair * 2 + wh] = conv;
            }
        }
        __syncthreads();   // barrier 2

        // ---- Phase 3: update last/done/doneflags ----
        if (!myDone) {
            if (last) {
                myDone = true;
                if (lane == 0 && wh == 0) ((volatile int*)sFlag)[pair] = 1;
            } else {
                done++;
                int both = sFlag[2 + pair * 2] & sFlag[2 + pair * 2 + 1];
                if (done >= niter || both) last = true;
            }
        }
        __syncthreads();   // barrier 3

        if (sFlag[0] && sFlag[1]) break;
    }
}

// ---------------------------------------------------------------------------
// Launch
// ---------------------------------------------------------------------------
extern "C" void kernel_launch(void* const* d_in, const int* in_sizes, int n_in,
                              void* d_out, int out_size)
{
    const float* x   = (const float*)d_in[0];
    const float* b   = (const float*)d_in[1];
    const float* W1  = (const float*)d_in[2];
    const float* b1  = (const float*)d_in[3];
    const float* W2  = (const float*)d_in[4];
    const float* b2  = (const float*)d_in[5];
    const float* W3  = (const float*)d_in[6];
    const float* b3  = (const float*)d_in[7];
    const float* A   = (const float*)d_in[8];
    const int* n_it  = (const int*)d_in[10];
    float* out = (float*)d_out;

    setup_kernel<<<1, 1024>>>(A);

    float* h1; cudaGetSymbolAddress((void**)&h1, g_H1);
    float* h2; cudaGetSymbolAddress((void**)&h2, g_H2);
    float* y;  cudaGetSymbolAddress((void**)&y,  g_Y);

    gemm_tf32_kernel<true ><<<dim3((HID  + 63) / 64, BB / 64), 256>>>(x,  W1, b1, h1, HID,  D_IN);
    gemm_tf32_kernel<true ><<<dim3((HID  + 63) / 64, BB / 64), 256>>>(h1, W2, b2, h2, HID,  HID);
    gemm_tf32_kernel<false><<<dim3((DIMV + 63) / 64, BB / 64), 256>>>(h2, W3, b3, y,  DIMV, HID);

    // Cooperative-pair tensor iteration: 128 CTAs x 128 thr (4 warps = 2 tasks).
    const int smem_bytes = SM_WORDS * 4;   // ~83KB
    cudaFuncSetAttribute(iter_mma_kernel, cudaFuncAttributeMaxDynamicSharedMemorySize, smem_bytes);
    iter_mma_kernel<<<BB / 32, 128, smem_bytes>>>(b, n_it, out);
}

// round 15
// speedup vs baseline: 1.4310x; 1.0305x over previous
#include <cuda_runtime.h>
#include <cstdint>
#include <cstring>

// Problem constants
#define BB     4096
#define D_IN   128
#define HID    200
#define DIMV   256
#define MM     32

#define B1_STRIDE 40    // pad: bank = 8tg+g (+8mt) -> conflict-free
#define Q2_STRIDE 264   // pad: bank = 8tg+g+8nt   -> conflict-free
#define B1_WORDS (128 * B1_STRIDE)   // 5120
#define Q2_WORDS (16 * Q2_STRIDE)    // 4224
#define EXCH_STRIDE 17               // 17*l mod 32 bijective -> conflict-free
#define EXCH_WORDS (4 * 32 * EXCH_STRIDE)   // 2176
#define SM_WORDS (2 * B1_WORDS + 2 * Q2_WORDS + EXCH_WORDS + 8)

// Scratch (device globals — no allocation allowed)
__device__ float g_H1[BB * HID];
__device__ float g_H2[BB * HID];
__device__ float g_Y [BB * DIMV];
__device__ float g_Q [MM * DIMV];
__device__ uint32_t g_B1hi[B1_WORDS];   // A^T packed bf16x2 (hi), fragment order
__device__ uint32_t g_B1lo[B1_WORDS];
__device__ uint32_t g_Q2hi[Q2_WORDS];   // Q packed bf16x2 (hi)
__device__ uint32_t g_Q2lo[Q2_WORDS];

// ---------------------------------------------------------------------------
// bf16 split-pack: x = hi + lo, packed bf16x2 {x0 low half, x1 high half}.
// ---------------------------------------------------------------------------
static __device__ __forceinline__ void bf16_split_pack(float x0, float x1,
                                                       uint32_t& hi, uint32_t& lo) {
    uint32_t h;
    asm("cvt.rn.bf16x2.f32 %0, %1, %2;" : "=r"(h) : "f"(x1), "f"(x0));
    float h0 = __uint_as_float(h << 16);
    float h1 = __uint_as_float(h & 0xFFFF0000u);
    float r0 = x0 - h0;
    float r1 = x1 - h1;
    uint32_t l;
    asm("cvt.rn.bf16x2.f32 %0, %1, %2;" : "=r"(l) : "f"(r1), "f"(r0));
    hi = h; lo = l;
}

static __device__ __forceinline__ void mma_bf16(float c[4], const uint32_t a[4],
                                                const uint32_t b[2]) {
    asm("mma.sync.aligned.m16n8k16.row.col.f32.bf16.bf16.f32 "
        "{%0,%1,%2,%3}, {%4,%5,%6,%7}, {%8,%9}, {%0,%1,%2,%3};"
        : "+f"(c[0]), "+f"(c[1]), "+f"(c[2]), "+f"(c[3])
        : "r"(a[0]), "r"(a[1]), "r"(a[2]), "r"(a[3]), "r"(b[0]), "r"(b[1]));
}

// tf32 helpers for the MLP (R12-proven)
static __device__ __forceinline__ void tf32_split(float x, uint32_t& hi, uint32_t& lo) {
    uint32_t h;
    asm("cvt.rna.tf32.f32 %0, %1;" : "=r"(h) : "f"(x));
    float l = x - __uint_as_float(h);
    uint32_t lw;
    asm("cvt.rna.tf32.f32 %0, %1;" : "=r"(lw) : "f"(l));
    hi = h; lo = lw;
}
static __device__ __forceinline__ void mma_tf32(float c[4], const uint32_t a[4], const uint32_t b[2]) {
    asm("mma.sync.aligned.m16n8k8.row.col.f32.tf32.tf32.f32 "
        "{%0,%1,%2,%3}, {%4,%5,%6,%7}, {%8,%9}, {%0,%1,%2,%3};"
        : "+f"(c[0]), "+f"(c[1]), "+f"(c[2]), "+f"(c[3])
        : "r"(a[0]), "r"(a[1]), "r"(a[2]), "r"(a[3]), "r"(b[0]), "r"(b[1]));
}

// ---------------------------------------------------------------------------
// Setup: G = A A^T + 1e-6 I, Gauss-Jordan inverse, Q = G^{-1} A, then pack
// A^T and Q into bf16-split fragment-ready arrays.
// ---------------------------------------------------------------------------
__global__ void setup_kernel(const float* __restrict__ A)
{
    __shared__ float G[32][65];
    __shared__ float fcol[32];
    const int t = threadIdx.x;
    const int i = t >> 5;
    const int j = t & 31;

    float s = 0.f;
    for (int k = 0; k < DIMV; k++)
        s += A[i * DIMV + k] * A[j * DIMV + k];
    G[i][j]      = s + (i == j ? 1e-6f : 0.f);
    G[i][j + 32] = (i == j) ? 1.f : 0.f;
    __syncthreads();

    for (int k = 0; k < 32; k++) {
        if (j == 0) fcol[i] = G[i][k];
        __syncthreads();
        if (i == k) {
            float inv = 1.f / fcol[k];
            G[k][j]      *= inv;
            G[k][j + 32] *= inv;
        }
        __syncthreads();
        if (i != k) {
            float f = fcol[i];
            G[i][j]      -= f * G[k][j];
            G[i][j + 32] -= f * G[k][j + 32];
        }
        __syncthreads();
    }

    for (int r = 0; r < 8; r++) {
        int idx = t + r * 1024;
        int m = idx >> 8;
        int d = idx & 255;
        float acc = 0.f;
        for (int k = 0; k < 32; k++)
            acc += G[m][32 + k] * A[k * DIMV + d];
        g_Q[m * DIMV + d] = acc;
    }
    __syncthreads();

    // Pack B1 = A^T: B1pack[d2][m] = bf16x2(A[m][2d2], A[m][2d2+1])
    // Pack Q2: Q2pack[m2][d] = bf16x2(Q[2m2][d], Q[2m2+1][d])
    for (int l = 0; l < 4; l++) {
        int idx = t + l * 1024;    // 0..4095
        {
            int d2 = idx >> 5, m = idx & 31;
            float a0 = A[m * DIMV + 2 * d2];
            float a1 = A[m * DIMV + 2 * d2 + 1];
            uint32_t hi, lo; bf16_split_pack(a0, a1, hi, lo);
            g_B1hi[d2 * B1_STRIDE + m] = hi;
            g_B1lo[d2 * B1_STRIDE + m] = lo;
        }
        {
            int m2 = idx >> 8, d = idx & 255;
            float q0 = g_Q[(2 * m2) * DIMV + d];
            float q1 = g_Q[(2 * m2 + 1) * DIMV + d];
            uint32_t hi, lo; bf16_split_pack(q0, q1, hi, lo);
            g_Q2hi[m2 * Q2_STRIDE + d] = hi;
            g_Q2lo[m2 * Q2_STRIDE + d] = lo;
        }
    }
}

// ---------------------------------------------------------------------------
// 3xTF32 tensor-core MLP GEMM (R12-proven, 18.6us/layer)
// ---------------------------------------------------------------------------
template<bool RELU>
__global__ __launch_bounds__(256)
void gemm_tf32_kernel(const float* __restrict__ X, const float* __restrict__ W,
                      const float* __restrict__ bias, float* __restrict__ Y,
                      int N, int K)
{
    __shared__ float Xs[64][36];
    __shared__ float Ws[32][72];
    const int t    = threadIdx.x;
    const int lane = t & 31;
    const int wid  = t >> 5;
    const int row0 = blockIdx.y * 64;
    const int col0 = blockIdx.x * 64;
    const int wm = (wid & 1) * 32;
    const int wn = (wid >> 1) * 16;
    const int lr = lane >> 2;
    const int lc = lane & 3;

    float c[2][2][4];
#pragma unroll
    for (int mt = 0; mt < 2; mt++)
#pragma unroll
        for (int nt = 0; nt < 2; nt++)
#pragma unroll
            for (int q = 0; q < 4; q++) c[mt][nt][q] = 0.f;

    const int nkt = (K + 31) / 32;
    for (int kt = 0; kt < nkt; kt++) {
        const int kbase = kt * 32;
#pragma unroll
        for (int l = 0; l < 2; l++) {
            int idx = t + l * 256;
            int r = idx >> 3;
            int q = idx & 7;
            int kk = kbase + q * 4;
            float4 v = make_float4(0.f, 0.f, 0.f, 0.f);
            if (kk + 4 <= K) v = *(const float4*)&X[(size_t)(row0 + r) * K + kk];
            *(float4*)&Xs[r][q * 4] = v;
        }
#pragma unroll
        for (int l = 0; l < 2; l++) {
            int idx = t + l * 256;
            int k = idx >> 4;
            int cq = idx & 15;
            int gk = kbase + k;
            int gc = col0 + cq * 4;
            float4 v = make_float4(0.f, 0.f, 0.f, 0.f);
            if (gk < K && gc + 4 <= N) v = *(const float4*)&W[(size_t)gk * N + gc];
            *(float4*)&Ws[k][cq * 4] = v;
        }
        __syncthreads();

#pragma unroll
        for (int ks = 0; ks < 4; ks++) {
            const int k0 = ks * 8;
            uint32_t ahi[2][4], alo[2][4];
#pragma unroll
            for (int mt = 0; mt < 2; mt++) {
                int rb = wm + mt * 16;
                float a0 = Xs[rb + lr    ][k0 + lc    ];
                float a1 = Xs[rb + lr + 8][k0 + lc    ];
                float a2 = Xs[rb + lr    ][k0 + lc + 4];
                float a3 = Xs[rb + lr + 8][k0 + lc + 4];
                tf32_split(a0, ahi[mt][0], alo[mt][0]);
                tf32_split(a1, ahi[mt][1], alo[mt][1]);
                tf32_split(a2, ahi[mt][2], alo[mt][2]);
                tf32_split(a3, ahi[mt][3], alo[mt][3]);
            }
            uint32_t bhi[2][2], blo[2][2];
#pragma unroll
            for (int nt = 0; nt < 2; nt++) {
                int cb = wn + nt * 8;
                float b0 = Ws[k0 + lc    ][cb + lr];
                float b1 = Ws[k0 + lc + 4][cb + lr];
                tf32_split(b0, bhi[nt][0], blo[nt][0]);
                tf32_split(b1, bhi[nt][1], blo[nt][1]);
            }
#pragma unroll
            for (int mt = 0; mt < 2; mt++)
#pragma unroll
                for (int nt = 0; nt < 2; nt++) {
                    mma_tf32(c[mt][nt], ahi[mt], bhi[nt]);
                    mma_tf32(c[mt][nt], ahi[mt], blo[nt]);
                    mma_tf32(c[mt][nt], alo[mt], bhi[nt]);
                }
        }
        __syncthreads();
    }

#pragma unroll
    for (int mt = 0; mt < 2; mt++) {
#pragma unroll
        for (int nt = 0; nt < 2; nt++) {
            int row = row0 + wm + mt * 16 + lr;
            int col = col0 + wn + nt * 8 + 2 * lc;
            if (col < N) {
                float bv0 = bias[col], bv1 = bias[col + 1];
                float v0 = c[mt][nt][0] + bv0;
                float v1 = c[mt][nt][1] + bv1;
                float v2 = c[mt][nt][2] + bv0;
                float v3 = c[mt][nt][3] + bv1;
                if (RELU) {
                    v0 = fmaxf(v0, 0.f); v1 = fmaxf(v1, 0.f);
                    v2 = fmaxf(v2, 0.f); v3 = fmaxf(v3, 0.f);
                }
                Y[(size_t)row * N + col]           = v0;
                Y[(size_t)row * N + col + 1]       = v1;
                Y[(size_t)(row + 8) * N + col]     = v2;
                Y[(size_t)(row + 8) * N + col + 1] = v3;
            }
        }
    }
}

// ---------------------------------------------------------------------------
// 4-warp cooperative tensor-core DR iteration.
// CTA = 128 thr = 4 warps = ONE 16-row task. Warp w owns:
//   GEMM1 k-chunks ks in [4w, 4w+4)  (consumes its own z n-tiles [8w,8w+8))
//   GEMM2 n-tiles  nt in [8w, 8w+8)
// Partial C1 summed via smem exchange (stride-17 -> conflict-free).
// Grid = 256 CTAs; smem 83KB -> 2 CTAs/SM -> 2 warps/SMSP (latency hidden),
// all 148 SMs active. CTA-uniform last/done from shared votes; 2 barriers/pass.
// ---------------------------------------------------------------------------
#define DR_TOL 5e-3f

__global__ __launch_bounds__(128)
void iter_mma_kernel(const float* __restrict__ bmat,
                     const int*   __restrict__ n_iter_ptr,
                     float* __restrict__ out)
{
    extern __shared__ uint32_t sm[];
    uint32_t* sB1hi = sm;
    uint32_t* sB1lo = sm + B1_WORDS;
    uint32_t* sQ2hi = sm + 2 * B1_WORDS;
    uint32_t* sQ2lo = sm + 2 * B1_WORDS + Q2_WORDS;
    float*    sExch = (float*)(sm + 2 * B1_WORDS + 2 * Q2_WORDS);   // [4][32][17]
    volatile int* sVote = (volatile int*)(sm + 2 * B1_WORDS + 2 * Q2_WORDS + EXCH_WORDS);

    const int t = threadIdx.x;
    for (int i = t; i < B1_WORDS; i += 128) { sB1hi[i] = g_B1hi[i]; sB1lo[i] = g_B1lo[i]; }
    for (int i = t; i < Q2_WORDS; i += 128) { sQ2hi[i] = g_Q2hi[i]; sQ2lo[i] = g_Q2lo[i]; }
    if (t < 4) ((volatile int*)sVote)[t] = 0;
    __syncthreads();

    const int wid   = t >> 5;         // 0..3
    const int lane  = t & 31;
    const int g     = lane >> 2;      // 0..7
    const int tg    = lane & 3;       // 0..3
    const int rowbase = blockIdx.x * 16;
    const int r0g = rowbase + g;
    const int r8g = rowbase + g + 8;

    float* myExch = &sExch[(wid * 32 + lane) * EXCH_STRIDE];

    // z: this warp's 8 n-tiles (global nt = 8*wid + j); C2-fragment layout.
    float z[8][4];
#pragma unroll
    for (int j = 0; j < 8; j++) {
        const int ntg = 8 * wid + j;
        float2 v0 = *(const float2*)&g_Y[(size_t)r0g * DIMV + 8 * ntg + 2 * tg];
        float2 v1 = *(const float2*)&g_Y[(size_t)r8g * DIMV + 8 * ntg + 2 * tg];
        z[j][0] = v0.x; z[j][1] = v0.y; z[j][2] = v1.x; z[j][3] = v1.y;
    }
    // b in C1-fragment layout (full; every warp computes r)
    float bv[4][4];
#pragma unroll
    for (int mt = 0; mt < 4; mt++) {
        float2 v0 = *(const float2*)&bmat[(size_t)r0g * MM + 8 * mt + 2 * tg];
        float2 v1 = *(const float2*)&bmat[(size_t)r8g * MM + 8 * mt + 2 * tg];
        bv[mt][0] = v0.x; bv[mt][1] = v0.y; bv[mt][2] = v1.x; bv[mt][3] = v1.y;
    }

    const int niter = *n_iter_ptr;
    const unsigned FULL = 0xffffffffu;
    bool last = (niter <= 0);
    int done = 0;

    for (;;) {
        // ---- Phase 1: partial GEMM1 over this warp's k-quarter ----
        {
            float chh[4][4], chl[4][4], clh[4][4];
#pragma unroll
            for (int mt = 0; mt < 4; mt++)
#pragma unroll
                for (int q = 0; q < 4; q++) { chh[mt][q] = 0.f; chl[mt][q] = 0.f; clh[mt][q] = 0.f; }

#pragma unroll
            for (int ksl = 0; ksl < 4; ksl++) {
                const int ks = 4 * wid + ksl;
                uint32_t ahi[4], alo[4];
                bf16_split_pack(z[2*ksl  ][0], z[2*ksl  ][1], ahi[0], alo[0]);
                bf16_split_pack(z[2*ksl  ][2], z[2*ksl  ][3], ahi[1], alo[1]);
                bf16_split_pack(z[2*ksl+1][0], z[2*ksl+1][1], ahi[2], alo[2]);
                bf16_split_pack(z[2*ksl+1][2], z[2*ksl+1][3], ahi[3], alo[3]);
#pragma unroll
                for (int mt = 0; mt < 4; mt++) {
                    const int i0 = (8 * ks + tg) * B1_STRIDE + 8 * mt + g;
                    const int i1 = (8 * ks + 4 + tg) * B1_STRIDE + 8 * mt + g;
                    uint32_t bh[2] = { sB1hi[i0], sB1hi[i1] };
                    uint32_t bl[2] = { sB1lo[i0], sB1lo[i1] };
                    mma_bf16(chh[mt], ahi, bh);
                    mma_bf16(chl[mt], ahi, bl);
                    mma_bf16(clh[mt], alo, bh);
                }
            }
#pragma unroll
            for (int mt = 0; mt < 4; mt++)
#pragma unroll
                for (int q = 0; q < 4; q++)
                    myExch[mt * 4 + q] = chh[mt][q] + chl[mt][q] + clh[mt][q];
        }
        __syncthreads();   // barrier 1

        // ---- Phase 2: sum partials, r, GEMM2 over own nt-quarter ----
        {
            float c1[4][4];
#pragma unroll
            for (int mt = 0; mt < 4; mt++)
#pragma unroll
                for (int q = 0; q < 4; q++) {
                    int e = mt * 4 + q;
                    c1[mt][q] = sExch[(0 * 32 + lane) * EXCH_STRIDE + e]
                              + sExch[(1 * 32 + lane) * EXCH_STRIDE + e]
                              + sExch[(2 * 32 + lane) * EXCH_STRIDE + e]
                              + sExch[(3 * 32 + lane) * EXCH_STRIDE + e];
                }

            uint32_t rhi[2][4], rlo[2][4];
#pragma unroll
            for (int ks2 = 0; ks2 < 2; ks2++) {
                float f0 = c1[2*ks2  ][0] - bv[2*ks2  ][0];
                float f1 = c1[2*ks2  ][1] - bv[2*ks2  ][1];
                float f2 = c1[2*ks2  ][2] - bv[2*ks2  ][2];
                float f3 = c1[2*ks2  ][3] - bv[2*ks2  ][3];
                float f4 = c1[2*ks2+1][0] - bv[2*ks2+1][0];
                float f5 = c1[2*ks2+1][1] - bv[2*ks2+1][1];
                float f6 = c1[2*ks2+1][2] - bv[2*ks2+1][2];
                float f7 = c1[2*ks2+1][3] - bv[2*ks2+1][3];
                bf16_split_pack(f0, f1, rhi[ks2][0], rlo[ks2][0]);
                bf16_split_pack(f2, f3, rhi[ks2][1], rlo[ks2][1]);
                bf16_split_pack(f4, f5, rhi[ks2][2], rlo[ks2][2]);
                bf16_split_pack(f6, f7, rhi[ks2][3], rlo[ks2][3]);
            }

            float dmax = 0.f;
#pragma unroll
            for (int j = 0; j < 8; j++) {
                const int ntg = 8 * wid + j;
                float chh2[4] = {0.f,0.f,0.f,0.f}, chl2[4] = {0.f,0.f,0.f,0.f}, clh2[4] = {0.f,0.f,0.f,0.f};
#pragma unroll
                for (int ks2 = 0; ks2 < 2; ks2++) {
                    const int i0 = (8 * ks2 + tg) * Q2_STRIDE + 8 * ntg + g;
                    const int i1 = (8 * ks2 + 4 + tg) * Q2_STRIDE + 8 * ntg + g;
                    uint32_t bh[2] = { sQ2hi[i0], sQ2hi[i1] };
                    uint32_t bl[2] = { sQ2lo[i0], sQ2lo[i1] };
                    mma_bf16(chh2, rhi[ks2], bh);
                    mma_bf16(chl2, rhi[ks2], bl);
                    mma_bf16(clh2, rlo[ks2], bh);
                }
                float c2[4];
#pragma unroll
                for (int q = 0; q < 4; q++) c2[q] = chh2[q] + chl2[q] + clh2[q];

                if (last) {
                    *(float2*)&out[(size_t)r0g * DIMV + 8 * ntg + 2 * tg] =
                        make_float2(z[j][0] - c2[0], z[j][1] - c2[1]);
                    *(float2*)&out[(size_t)r8g * DIMV + 8 * ntg + 2 * tg] =
                        make_float2(z[j][2] - c2[2], z[j][3] - c2[3]);
                } else {
#pragma unroll
                    for (int q = 0; q < 4; q++) {
                        float u = z[j][q] - c2[q];
                        float v = fminf(fmaxf(2.f * u - z[j][q], 0.f), 1.f);
                        float d = v - u;
                        z[j][q] = fmaf(1.7f, d, z[j][q]);
                        dmax = fmaxf(dmax, fabsf(d));
                    }
                }
            }
            if (!last) {
                int conv = __all_sync(FULL, dmax < DR_TOL) ? 1 : 0;
                if (lane == 0) ((volatile int*)sVote)[wid] = conv;
            }
        }
        __syncthreads();   // barrier 2

        if (last) break;
        done++;
        int allc = sVote[0] & sVote[1] & sVote[2] & sVote[3];
        if (done >= niter || allc) last = true;
    }
}

// ---------------------------------------------------------------------------
// Launch
// ---------------------------------------------------------------------------
extern "C" void kernel_launch(void* const* d_in, const int* in_sizes, int n_in,
                              void* d_out, int out_size)
{
    const float* x   = (const float*)d_in[0];
    const float* b   = (const float*)d_in[1];
    const float* W1  = (const float*)d_in[2];
    const float* b1  = (const float*)d_in[3];
    const float* W2  = (const float*)d_in[4];
    const float* b2  = (const float*)d_in[5];
    const float* W3  = (const float*)d_in[6];
    const float* b3  = (const float*)d_in[7];
    const float* A   = (const float*)d_in[8];
    const int* n_it  = (const int*)d_in[10];
    float* out = (float*)d_out;

    setup_kernel<<<1, 1024>>>(A);

    float* h1; cudaGetSymbolAddress((void**)&h1, g_H1);
    float* h2; cudaGetSymbolAddress((void**)&h2, g_H2);
    float* y;  cudaGetSymbolAddress((void**)&y,  g_Y);

    gemm_tf32_kernel<true ><<<dim3((HID  + 63) / 64, BB / 64), 256>>>(x,  W1, b1, h1, HID,  D_IN);
    gemm_tf32_kernel<true ><<<dim3((HID  + 63) / 64, BB / 64), 256>>>(h1, W2, b2, h2, HID,  HID);
    gemm_tf32_kernel<false><<<dim3((DIMV + 63) / 64, BB / 64), 256>>>(h2, W3, b3, y,  DIMV, HID);

    // 4-warp cooperative tensor iteration: 256 CTAs x 128 thr, 2 CTAs/SM.
    const int smem_bytes = SM_WORDS * 4;   // ~83KB
    cudaFuncSetAttribute(iter_mma_kernel, cudaFuncAttributeMaxDynamicSharedMemorySize, smem_bytes);
    iter_mma_kernel<<<BB / 16, 128, smem_bytes>>>(b, n_it, out);
}